// round 10
// baseline (speedup 1.0000x reference)
#include <cuda_runtime.h>
#include <cuda_bf16.h>
#include <cstdint>
#include <stdint.h>
#include <math.h>

// ---------------------------------------------------------------------------
// GCN 3-layer. Round 9: mma.sync tf32 (2-term split) GEMMs with FRAGMENT-ORDER
// shared memory: A frags load as one LDS.128, B frags as one LDS.64, both
// conflict-free. (tcgen05 rejected by this toolchain's ptxas target.)
// CSR gather SpMM + fused spmm16+log_softmax unchanged.
// ---------------------------------------------------------------------------

#define NN 50000
#define EE 800000

__device__ float g_support[NN * 128];
__device__ float g_h1[NN * 128];
__device__ float g_h2[NN * 64];
__device__ int   g_counts[NN + 1];
__device__ int   g_offsets[NN + 1];
__device__ int   g_cursor[NN];
__device__ int   g_col[EE];
__device__ float g_val[EE];

// ------------------------------ CSR build ----------------------------------

__global__ void hist_kernel(const int* __restrict__ src, int* __restrict__ counts, int E) {
    int i = blockIdx.x * blockDim.x + threadIdx.x;
    if (i < E) atomicAdd(&counts[src[i]], 1);
}

__global__ void scan_kernel(const int* __restrict__ counts, int* __restrict__ offsets, int n) {
    const int T = 1024;
    __shared__ int wsum[32];
    int tid = threadIdx.x;
    int per = (n + T - 1) / T;
    int beg = tid * per;
    int end = min(beg + per, n);
    int sum = 0;
    for (int i = beg; i < end; i++) sum += counts[i];
    int lane = tid & 31, wid = tid >> 5;
    int v = sum;
    #pragma unroll
    for (int off = 1; off < 32; off <<= 1) {
        int t2 = __shfl_up_sync(0xffffffffu, v, off);
        if (lane >= off) v += t2;
    }
    if (lane == 31) wsum[wid] = v;
    __syncthreads();
    if (wid == 0) {
        int w = wsum[lane];
        #pragma unroll
        for (int off = 1; off < 32; off <<= 1) {
            int t2 = __shfl_up_sync(0xffffffffu, w, off);
            if (lane >= off) w += t2;
        }
        wsum[lane] = w;
    }
    __syncthreads();
    int pre = v - sum + (wid > 0 ? wsum[wid - 1] : 0);
    int run = pre;
    for (int i = beg; i < end; i++) { offsets[i] = run; run += counts[i]; }
    if (end == n) offsets[n] = run;
}

__global__ void scatter_kernel(const int* __restrict__ src, const int* __restrict__ dst,
                               const float* __restrict__ ev,
                               const int* __restrict__ offsets, int* __restrict__ cursor,
                               int* __restrict__ col, float* __restrict__ val, int E) {
    int i = blockIdx.x * blockDim.x + threadIdx.x;
    if (i < E) {
        int s = src[i];
        int pos = offsets[s] + atomicAdd(&cursor[s], 1);
        col[pos] = dst[i];
        val[pos] = ev[i];
    }
}

// ------------------------------ tf32 GEMM ----------------------------------
// C[M,N] = A[M,K] @ B[K,N] (+bias). mma m16n8k8 tf32 with hi/lo split
// (3 MMAs per logical MMA). Shared memory holds tiles in FRAGMENT ORDER:
//   A_frag[k8][rb][lane][4]  (a0..a3 of mma operand, one LDS.128 per frag)
//   B_frag[k8][cb][lane][2]  (b0,b1 of mma operand, one LDS.64 per frag)
// Requires N == BN (grid.x == 1), K % 4 == 0.

__device__ __forceinline__ void split_tf32(float x, unsigned& hi, unsigned& lo) {
    unsigned h;
    asm("cvt.rna.tf32.f32 %0, %1;" : "=r"(h) : "f"(x));
    float r = x - __uint_as_float(h);
    unsigned l;
    asm("cvt.rna.tf32.f32 %0, %1;" : "=r"(l) : "f"(r));
    hi = h; lo = l;
}

#define MMA_TF32(c, a, b)                                                    \
    asm volatile(                                                            \
        "mma.sync.aligned.m16n8k8.row.col.f32.tf32.tf32.f32 "                \
        "{%0,%1,%2,%3}, {%4,%5,%6,%7}, {%8,%9}, {%0,%1,%2,%3};\n"            \
        : "+f"((c)[0]), "+f"((c)[1]), "+f"((c)[2]), "+f"((c)[3])             \
        : "r"((a)[0]), "r"((a)[1]), "r"((a)[2]), "r"((a)[3]),                \
          "r"((b)[0]), "r"((b)[1]))

constexpr int gemm_smem_bytes(int BM, int BN, int BK) {
    int K8 = BK / 8, RBc = BM / 16, CBc = BN / 8;
    int afrag = K8 * RBc * 128;   // floats per buffer
    int bfrag = K8 * CBc * 64;
    return (2 * 2 * afrag + 2 * 2 * bfrag) * 4;  // hi/lo x 2 buffers, 4B each
}

template <int BM, int BN, int BK, int WARPS_M, int WARPS_N, bool BIAS>
__global__ void __launch_bounds__(32 * WARPS_M * WARPS_N)
tf32_gemm_kernel(int M, int N, int K,
                 const float* __restrict__ A, const float* __restrict__ B,
                 const float* __restrict__ bias, float* __restrict__ C) {
    constexpr int THREADS = 32 * WARPS_M * WARPS_N;
    constexpr int WM = BM / WARPS_M, WN = BN / WARPS_N;
    constexpr int MT = WM / 16, NT = WN / 8;
    constexpr int K8 = BK / 8;
    constexpr int RBc = BM / 16, CBc = BN / 8;
    constexpr int AFRAG = K8 * RBc * 128;   // floats per buffer
    constexpr int BFRAG = K8 * CBc * 64;
    constexpr int A4 = BM * BK / 4, B4 = BK * BN / 4;
    constexpr int RA = (A4 + THREADS - 1) / THREADS;
    constexpr int RB = (B4 + THREADS - 1) / THREADS;

    extern __shared__ float fsm[];
    float* Ah = fsm;                   // [2][AFRAG]
    float* Al = Ah + 2 * AFRAG;
    float* Bh = Al + 2 * AFRAG;        // [2][BFRAG]
    float* Bl = Bh + 2 * BFRAG;

    const int tid = threadIdx.x;
    const int warp = tid >> 5, lane = tid & 31;
    const int wm = (warp / WARPS_N) * WM;      // row base of warp
    const int wn = (warp % WARPS_N) * WN;      // col base of warp
    const int rb0 = wm >> 4;                   // 16-row block index
    const int cb0 = wn >> 3;                   // 8-col block index
    const int g = lane >> 2, t = lane & 3;
    const int row0 = blockIdx.y * BM;

    float acc[MT][NT][4];
    #pragma unroll
    for (int mi = 0; mi < MT; mi++)
        #pragma unroll
        for (int ni = 0; ni < NT; ni++)
            #pragma unroll
            for (int q = 0; q < 4; q++) acc[mi][ni][q] = 0.f;

    float4 ra[RA], rb[RB];
    const int ntiles = (K + BK - 1) / BK;

    auto load_tile = [&](int k0t) {
        #pragma unroll
        for (int i = 0; i < RA; i++) {
            int idx = tid + i * THREADS;
            float4 v = make_float4(0.f, 0.f, 0.f, 0.f);
            if (idx < A4) {
                int r = idx / (BK / 4), q = idx % (BK / 4);
                int gm = row0 + r, gk = k0t + q * 4;
                if (gm < M && gk + 4 <= K)
                    v = *(const float4*)(A + (long)gm * K + gk);
            }
            ra[i] = v;
        }
        #pragma unroll
        for (int i = 0; i < RB; i++) {
            int idx = tid + i * THREADS;
            float4 v = make_float4(0.f, 0.f, 0.f, 0.f);
            if (idx < B4) {
                int r = idx / (BN / 4), q = idx % (BN / 4);
                int gk = k0t + r;
                if (gk < K)
                    v = *(const float4*)(B + (long)gk * N + q * 4);
            }
            rb[i] = v;
        }
    };

    // store register tile into fragment-order smem (with tf32 hi/lo split)
    auto store_tile = [&](int b) {
        float* ahb = Ah + b * AFRAG; float* alb = Al + b * AFRAG;
        float* bhb = Bh + b * BFRAG; float* blb = Bl + b * BFRAG;
        #pragma unroll
        for (int i = 0; i < RA; i++) {
            int idx = tid + i * THREADS;
            if (idx < A4) {
                int r = idx / (BK / 4), q = idx % (BK / 4);
                int k0 = q * 4;
                int rbx = r >> 4, rr = r & 15;
                int gg = rr & 7, half = rr >> 3;
                int k8 = k0 >> 3, khalf = (k0 >> 2) & 1;
                int slot = half + 2 * khalf;
                float vv[4] = {ra[i].x, ra[i].y, ra[i].z, ra[i].w};
                #pragma unroll
                for (int j = 0; j < 4; j++) {
                    unsigned h, l;
                    split_tf32(vv[j], h, l);
                    int fidx = ((k8 * RBc + rbx) * 32 + gg * 4 + j) * 4 + slot;
                    ahb[fidx] = __uint_as_float(h);
                    alb[fidx] = __uint_as_float(l);
                }
            }
        }
        #pragma unroll
        for (int i = 0; i < RB; i++) {
            int idx = tid + i * THREADS;
            if (idx < B4) {
                int kr = idx / (BN / 4), q = idx % (BN / 4);
                int c0 = q * 4;
                int k8 = kr >> 3, tt = kr & 3, khalf = (kr >> 2) & 1;
                float vv[4] = {rb[i].x, rb[i].y, rb[i].z, rb[i].w};
                #pragma unroll
                for (int j = 0; j < 4; j++) {
                    unsigned h, l;
                    split_tf32(vv[j], h, l);
                    int c = c0 + j;
                    int cbx = c >> 3, gg = c & 7;
                    int fidx = ((k8 * CBc + cbx) * 32 + gg * 4 + tt) * 2 + khalf;
                    bhb[fidx] = __uint_as_float(h);
                    blb[fidx] = __uint_as_float(l);
                }
            }
        }
    };

    load_tile(0);
    store_tile(0);
    __syncthreads();

    for (int tt2 = 0; tt2 < ntiles; tt2++) {
        if (tt2 + 1 < ntiles) load_tile((tt2 + 1) * BK);

        const float* cAh = Ah + (tt2 & 1) * AFRAG;
        const float* cAl = Al + (tt2 & 1) * AFRAG;
        const float* cBh = Bh + (tt2 & 1) * BFRAG;
        const float* cBl = Bl + (tt2 & 1) * BFRAG;

        #pragma unroll
        for (int k8 = 0; k8 < K8; k8++) {
            float4 fah[MT], fal[MT];
            float2 fbh[NT], fbl[NT];
            #pragma unroll
            for (int mi = 0; mi < MT; mi++) {
                int base = ((k8 * RBc + rb0 + mi) * 32 + lane) * 4;
                fah[mi] = *(const float4*)(cAh + base);
                fal[mi] = *(const float4*)(cAl + base);
            }
            #pragma unroll
            for (int ni = 0; ni < NT; ni++) {
                int base = ((k8 * CBc + cb0 + ni) * 32 + lane) * 2;
                fbh[ni] = *(const float2*)(cBh + base);
                fbl[ni] = *(const float2*)(cBl + base);
            }
            #pragma unroll
            for (int mi = 0; mi < MT; mi++)
                #pragma unroll
                for (int ni = 0; ni < NT; ni++) {
                    const unsigned* ah = (const unsigned*)&fah[mi];
                    const unsigned* al = (const unsigned*)&fal[mi];
                    const unsigned* bh = (const unsigned*)&fbh[ni];
                    const unsigned* bl = (const unsigned*)&fbl[ni];
                    MMA_TF32(acc[mi][ni], ah, bh);
                    MMA_TF32(acc[mi][ni], al, bh);
                    MMA_TF32(acc[mi][ni], ah, bl);
                }
        }

        if (tt2 + 1 < ntiles) store_tile((tt2 + 1) & 1);
        __syncthreads();
    }

    // epilogue
    #pragma unroll
    for (int mi = 0; mi < MT; mi++) {
        int r = row0 + wm + mi * 16 + g;
        #pragma unroll
        for (int ni = 0; ni < NT; ni++) {
            int c = wn + ni * 8 + 2 * t;
            float bx = 0.f, by = 0.f;
            if (BIAS) { bx = bias[c]; by = bias[c + 1]; }
            if (r < M)
                *(float2*)(C + (long)r * N + c) = make_float2(acc[mi][ni][0] + bx, acc[mi][ni][1] + by);
            if (r + 8 < M)
                *(float2*)(C + (long)(r + 8) * N + c) = make_float2(acc[mi][ni][2] + bx, acc[mi][ni][3] + by);
        }
    }
}

// ------------------------------ CSR SpMM -----------------------------------

template <bool RELU>
__global__ void spmm128_kernel(const float* __restrict__ support,
                               const int* __restrict__ offsets,
                               const int* __restrict__ col,
                               const float* __restrict__ val,
                               const float* __restrict__ bias,
                               float* __restrict__ out, int n) {
    int warp = (blockIdx.x * blockDim.x + threadIdx.x) >> 5;
    int lane = threadIdx.x & 31;
    if (warp >= n) return;
    int start = offsets[warp], end = offsets[warp + 1];
    const float4* sup4 = (const float4*)support;
    float4 acc = make_float4(0.f, 0.f, 0.f, 0.f);
    int j = start;
    for (; j + 2 <= end; j += 2) {
        int c0 = col[j], c1 = col[j + 1];
        float w0 = val[j], w1 = val[j + 1];
        float4 s0 = sup4[c0 * 32 + lane];
        float4 s1 = sup4[c1 * 32 + lane];
        acc.x += w0 * s0.x + w1 * s1.x;
        acc.y += w0 * s0.y + w1 * s1.y;
        acc.z += w0 * s0.z + w1 * s1.z;
        acc.w += w0 * s0.w + w1 * s1.w;
    }
    if (j < end) {
        int c = col[j]; float w = val[j];
        float4 s = sup4[c * 32 + lane];
        acc.x += w * s.x; acc.y += w * s.y; acc.z += w * s.z; acc.w += w * s.w;
    }
    float4 bb = ((const float4*)bias)[lane];
    acc.x += bb.x; acc.y += bb.y; acc.z += bb.z; acc.w += bb.w;
    if (RELU) {
        acc.x = fmaxf(acc.x, 0.f); acc.y = fmaxf(acc.y, 0.f);
        acc.z = fmaxf(acc.z, 0.f); acc.w = fmaxf(acc.w, 0.f);
    }
    ((float4*)out)[warp * 32 + lane] = acc;
}

template <bool RELU>
__global__ void spmm64_kernel(const float* __restrict__ support,
                              const int* __restrict__ offsets,
                              const int* __restrict__ col,
                              const float* __restrict__ val,
                              const float* __restrict__ bias,
                              float* __restrict__ out, int n) {
    int warp = (blockIdx.x * blockDim.x + threadIdx.x) >> 5;
    int lane = threadIdx.x & 31;
    if (warp >= n) return;
    int start = offsets[warp], end = offsets[warp + 1];
    const float2* sup2 = (const float2*)support;
    float2 acc = make_float2(0.f, 0.f);
    int j = start;
    for (; j + 2 <= end; j += 2) {
        int c0 = col[j], c1 = col[j + 1];
        float w0 = val[j], w1 = val[j + 1];
        float2 s0 = sup2[c0 * 32 + lane];
        float2 s1 = sup2[c1 * 32 + lane];
        acc.x += w0 * s0.x + w1 * s1.x;
        acc.y += w0 * s0.y + w1 * s1.y;
    }
    if (j < end) {
        int c = col[j]; float w = val[j];
        float2 s = sup2[c * 32 + lane];
        acc.x += w * s.x; acc.y += w * s.y;
    }
    float2 bb = ((const float2*)bias)[lane];
    acc.x += bb.x; acc.y += bb.y;
    if (RELU) { acc.x = fmaxf(acc.x, 0.f); acc.y = fmaxf(acc.y, 0.f); }
    ((float2*)out)[warp * 32 + lane] = acc;
}

__global__ void spmm16_lsm_kernel(const float* __restrict__ support,
                                  const int* __restrict__ offsets,
                                  const int* __restrict__ col,
                                  const float* __restrict__ val,
                                  const float* __restrict__ bias,
                                  float* __restrict__ out, int n) {
    int t = blockIdx.x * blockDim.x + threadIdx.x;
    int grp = t >> 4;
    int sub = t & 15;
    bool active = grp < n;
    int g2 = active ? grp : (n - 1);
    int start = offsets[g2], end = offsets[g2 + 1];
    float acc = 0.f;
    for (int j = start; j < end; j++)
        acc += val[j] * support[col[j] * 16 + sub];
    acc += bias[sub];
    float m = acc;
    #pragma unroll
    for (int off = 8; off >= 1; off >>= 1)
        m = fmaxf(m, __shfl_xor_sync(0xffffffffu, m, off, 16));
    float s = expf(acc - m);
    #pragma unroll
    for (int off = 8; off >= 1; off >>= 1)
        s += __shfl_xor_sync(0xffffffffu, s, off, 16);
    if (active) out[grp * 16 + sub] = acc - (logf(s) + m);
}

// ------------------------------ launch -------------------------------------

extern "C" void kernel_launch(void* const* d_in, const int* in_sizes, int n_in,
                              void* d_out, int out_size) {
    const float* x  = (const float*)d_in[0];
    const float* ev = (const float*)d_in[1];
    const float* W1 = (const float*)d_in[2];
    const float* b1 = (const float*)d_in[3];
    const float* W2 = (const float*)d_in[4];
    const float* b2 = (const float*)d_in[5];
    const float* W3 = (const float*)d_in[6];
    const float* b3 = (const float*)d_in[7];
    const float* We = (const float*)d_in[8];
    const float* be = (const float*)d_in[9];
    const int* esrc = (const int*)d_in[10];
    const int* edst = (const int*)d_in[11];

    const int N = NN;
    const int E = in_sizes[10];

    float* out1 = (float*)d_out;
    float* out2 = (float*)d_out + (long)N * 16;

    float *p_support, *p_h1, *p_h2, *p_val;
    int *p_counts, *p_offsets, *p_cursor, *p_col;
    cudaGetSymbolAddress((void**)&p_support, g_support);
    cudaGetSymbolAddress((void**)&p_h1, g_h1);
    cudaGetSymbolAddress((void**)&p_h2, g_h2);
    cudaGetSymbolAddress((void**)&p_counts, g_counts);
    cudaGetSymbolAddress((void**)&p_offsets, g_offsets);
    cudaGetSymbolAddress((void**)&p_cursor, g_cursor);
    cudaGetSymbolAddress((void**)&p_col, g_col);
    cudaGetSymbolAddress((void**)&p_val, g_val);

    constexpr int S1 = gemm_smem_bytes(128, 128, 16);  // 64 KB
    constexpr int S2 = gemm_smem_bytes(128, 64, 16);   // 48 KB
    constexpr int S3 = gemm_smem_bytes(128, 16, 16);   // 36 KB
    cudaFuncSetAttribute(tf32_gemm_kernel<128, 128, 16, 2, 4, false>,
                         cudaFuncAttributeMaxDynamicSharedMemorySize, S1);
    cudaFuncSetAttribute(tf32_gemm_kernel<128, 64, 16, 4, 2, false>,
                         cudaFuncAttributeMaxDynamicSharedMemorySize, S2);
    cudaFuncSetAttribute(tf32_gemm_kernel<128, 64, 16, 4, 2, true>,
                         cudaFuncAttributeMaxDynamicSharedMemorySize, S2);
    cudaFuncSetAttribute(tf32_gemm_kernel<128, 16, 16, 8, 1, false>,
                         cudaFuncAttributeMaxDynamicSharedMemorySize, S3);

    // ---- CSR build ----
    cudaMemsetAsync(p_counts, 0, (N + 1) * sizeof(int), 0);
    cudaMemsetAsync(p_cursor, 0, N * sizeof(int), 0);
    hist_kernel<<<(E + 255) / 256, 256>>>(esrc, p_counts, E);
    scan_kernel<<<1, 1024>>>(p_counts, p_offsets, N);
    scatter_kernel<<<(E + 255) / 256, 256>>>(esrc, edst, ev, p_offsets, p_cursor, p_col, p_val, E);

    dim3 grid(1, (N + 127) / 128);

    // ---- layer 1: support = x@W1 [N,128]; h1 = relu(agg + b1) ----
    tf32_gemm_kernel<128, 128, 16, 2, 4, false><<<grid, 256, S1>>>(N, 128, 500, x, W1, nullptr, p_support);
    spmm128_kernel<true><<<(N * 32 + 255) / 256, 256>>>(p_support, p_offsets, p_col, p_val, b1, p_h1, N);

    // ---- layer 2: support = h1@W2 [N,64]; h2 = relu(agg + b2) ----
    tf32_gemm_kernel<128, 64, 16, 4, 2, false><<<grid, 256, S2>>>(N, 64, 128, p_h1, W2, nullptr, p_support);
    spmm64_kernel<true><<<(N * 32 + 255) / 256, 256>>>(p_support, p_offsets, p_col, p_val, b2, p_h2, N);

    // ---- layer 3: support = h2@W3 [N,16]; out1 = log_softmax(agg + b3) ----
    tf32_gemm_kernel<128, 16, 16, 8, 1, false><<<grid, 256, S3>>>(N, 16, 64, p_h2, W3, nullptr, p_support);
    spmm16_lsm_kernel<<<(N * 16 + 255) / 256, 256>>>(p_support, p_offsets, p_col, p_val, b3, out1, N);

    // ---- head 2: out2 = h2@We + be ----
    tf32_gemm_kernel<128, 64, 16, 4, 2, true><<<grid, 256, S2>>>(N, 64, 64, p_h2, We, be, out2);
}

// round 11
// speedup vs baseline: 1.5657x; 1.5657x over previous
#include <cuda_runtime.h>
#include <cuda_bf16.h>
#include <cstdint>
#include <stdint.h>
#include <math.h>

// ---------------------------------------------------------------------------
// GCN 3-layer. Round 10: all dense GEMMs on mma.sync m16n8k16 BF16 with
// 3-term hi/lo split (half the HMMA count + half the fragment LDS of the tf32
// k8 path). GEMM1 runs 512-thread CTAs for 16 warps/SM. CSR gather SpMM +
// fused spmm16+log_softmax as in the 310us config.
// ---------------------------------------------------------------------------

#define NN 50000
#define EE 800000

__device__ float g_support[NN * 128];
__device__ float g_h1[NN * 128];
__device__ float g_h2[NN * 64];
__device__ int   g_counts[NN + 1];
__device__ int   g_offsets[NN + 1];
__device__ int   g_cursor[NN];
__device__ int   g_col[EE];
__device__ float g_val[EE];

// ------------------------------ CSR build ----------------------------------

__global__ void hist_kernel(const int* __restrict__ src, int* __restrict__ counts, int E) {
    int i = blockIdx.x * blockDim.x + threadIdx.x;
    if (i < E) atomicAdd(&counts[src[i]], 1);
}

__global__ void scan_kernel(const int* __restrict__ counts, int* __restrict__ offsets, int n) {
    const int T = 1024;
    __shared__ int wsum[32];
    int tid = threadIdx.x;
    int per = (n + T - 1) / T;
    int beg = tid * per;
    int end = min(beg + per, n);
    int sum = 0;
    for (int i = beg; i < end; i++) sum += counts[i];
    int lane = tid & 31, wid = tid >> 5;
    int v = sum;
    #pragma unroll
    for (int off = 1; off < 32; off <<= 1) {
        int t2 = __shfl_up_sync(0xffffffffu, v, off);
        if (lane >= off) v += t2;
    }
    if (lane == 31) wsum[wid] = v;
    __syncthreads();
    if (wid == 0) {
        int w = wsum[lane];
        #pragma unroll
        for (int off = 1; off < 32; off <<= 1) {
            int t2 = __shfl_up_sync(0xffffffffu, w, off);
            if (lane >= off) w += t2;
        }
        wsum[lane] = w;
    }
    __syncthreads();
    int pre = v - sum + (wid > 0 ? wsum[wid - 1] : 0);
    int run = pre;
    for (int i = beg; i < end; i++) { offsets[i] = run; run += counts[i]; }
    if (end == n) offsets[n] = run;
}

__global__ void scatter_kernel(const int* __restrict__ src, const int* __restrict__ dst,
                               const float* __restrict__ ev,
                               const int* __restrict__ offsets, int* __restrict__ cursor,
                               int* __restrict__ col, float* __restrict__ val, int E) {
    int i = blockIdx.x * blockDim.x + threadIdx.x;
    if (i < E) {
        int s = src[i];
        int pos = offsets[s] + atomicAdd(&cursor[s], 1);
        col[pos] = dst[i];
        val[pos] = ev[i];
    }
}

// ------------------------------ bf16 GEMM ----------------------------------
// C[M,N] = A[M,K] @ B[K,N] (+bias). mma m16n8k16 bf16 with hi/lo split
// (3 MMAs per logical k16). Values live in smem as bf16x2 pairs:
//   Ah/Al: [BM][SA32] uint32, pair p = (k=2p low half, k=2p+1 high half)
//   Bh/Bl: [BK/2][SB32] uint32, row p col c = (B[2p][c] low, B[2p+1][c] high)
// Requires N == BN (grid.x == 1), K even.

__device__ __forceinline__ uint32_t pack2_bf16(float klo, float khi) {
    // result = { bf16(khi) << 16 | bf16(klo) }
    uint32_t r;
    asm("cvt.rn.bf16x2.f32 %0, %1, %2;" : "=r"(r) : "f"(khi), "f"(klo));
    return r;
}
__device__ __forceinline__ float bf16_round(float x) {
    return __bfloat162float(__float2bfloat16(x));
}

#define MMA_BF16(c, a, b)                                                    \
    asm volatile(                                                            \
        "mma.sync.aligned.m16n8k16.row.col.f32.bf16.bf16.f32 "               \
        "{%0,%1,%2,%3}, {%4,%5,%6,%7}, {%8,%9}, {%0,%1,%2,%3};\n"            \
        : "+f"((c)[0]), "+f"((c)[1]), "+f"((c)[2]), "+f"((c)[3])             \
        : "r"((a)[0]), "r"((a)[1]), "r"((a)[2]), "r"((a)[3]),                \
          "r"((b)[0]), "r"((b)[1]))

constexpr int gemm_smem_bytes(int BM, int BN, int BK) {
    int SA32 = BK / 2 + 4, SB32 = BN + 8;
    return (2 * BM * SA32 + 2 * (BK / 2) * SB32) * 4;
}

template <int BM, int BN, int BK, int WARPS_M, int WARPS_N, bool BIAS>
__global__ void __launch_bounds__(32 * WARPS_M * WARPS_N,
                                  (WARPS_M * WARPS_N <= 8) ? 2 : 1)
bf16_gemm_kernel(int M, int N, int K,
                 const float* __restrict__ A, const float* __restrict__ B,
                 const float* __restrict__ bias, float* __restrict__ C) {
    constexpr int THREADS = 32 * WARPS_M * WARPS_N;
    constexpr int WM = BM / WARPS_M, WN = BN / WARPS_N;
    constexpr int MT = WM / 16, NT = WN / 8;
    constexpr int SA32 = BK / 2 + 4;
    constexpr int SB32 = BN + 8;
    constexpr int AITEMS = BM * BK / 4;                 // float4 loads of A
    constexpr int BITEMS = (BK / 2) * (BN / 4);         // pair items of B
    constexpr int RA = (AITEMS + THREADS - 1) / THREADS;
    constexpr int RBn = (BITEMS + THREADS - 1) / THREADS;

    extern __shared__ uint32_t usm[];
    uint32_t* Ah = usm;
    uint32_t* Al = Ah + BM * SA32;
    uint32_t* Bh = Al + BM * SA32;
    uint32_t* Bl = Bh + (BK / 2) * SB32;

    const int tid = threadIdx.x;
    const int warp = tid >> 5, lane = tid & 31;
    const int wm = (warp / WARPS_N) * WM;
    const int wn = (warp % WARPS_N) * WN;
    const int g = lane >> 2, t = lane & 3;
    const int row0 = blockIdx.y * BM;

    float acc[MT][NT][4];
    #pragma unroll
    for (int mi = 0; mi < MT; mi++)
        #pragma unroll
        for (int ni = 0; ni < NT; ni++)
            #pragma unroll
            for (int q = 0; q < 4; q++) acc[mi][ni][q] = 0.f;

    float4 ra[RA], rb0[RBn], rb1[RBn];
    const int ntiles = (K + BK - 1) / BK;

    auto load_tile = [&](int k0t) {
        #pragma unroll
        for (int i = 0; i < RA; i++) {
            int idx = tid + i * THREADS;
            float4 v = make_float4(0.f, 0.f, 0.f, 0.f);
            if (idx < AITEMS) {
                int r = idx / (BK / 4), q = idx % (BK / 4);
                int gm = row0 + r, gk = k0t + q * 4;
                if (gm < M && gk + 4 <= K)
                    v = *(const float4*)(A + (long)gm * K + gk);
            }
            ra[i] = v;
        }
        #pragma unroll
        for (int i = 0; i < RBn; i++) {
            int idx = tid + i * THREADS;
            float4 v0 = make_float4(0.f, 0.f, 0.f, 0.f);
            float4 v1 = v0;
            if (idx < BITEMS) {
                int kp = idx / (BN / 4), q = idx % (BN / 4);
                int gk0 = k0t + 2 * kp;
                if (gk0 < K)     v0 = *(const float4*)(B + (long)gk0 * N + q * 4);
                if (gk0 + 1 < K) v1 = *(const float4*)(B + (long)(gk0 + 1) * N + q * 4);
            }
            rb0[i] = v0; rb1[i] = v1;
        }
    };

    auto store_tile = [&]() {
        #pragma unroll
        for (int i = 0; i < RA; i++) {
            int idx = tid + i * THREADS;
            if (idx < AITEMS) {
                int r = idx / (BK / 4), q = idx % (BK / 4);
                float4 v = ra[i];
                float hx = bf16_round(v.x), hy = bf16_round(v.y);
                float hz = bf16_round(v.z), hw = bf16_round(v.w);
                uint2 ph, pl;
                ph.x = pack2_bf16(v.x, v.y);
                ph.y = pack2_bf16(v.z, v.w);
                pl.x = pack2_bf16(v.x - hx, v.y - hy);
                pl.y = pack2_bf16(v.z - hz, v.w - hw);
                int base = r * SA32 + q * 2;
                *(uint2*)(Ah + base) = ph;
                *(uint2*)(Al + base) = pl;
            }
        }
        #pragma unroll
        for (int i = 0; i < RBn; i++) {
            int idx = tid + i * THREADS;
            if (idx < BITEMS) {
                int kp = idx / (BN / 4), q = idx % (BN / 4);
                float4 v0 = rb0[i], v1 = rb1[i];
                float a0 = v0.x, a1 = v0.y, a2 = v0.z, a3 = v0.w;
                float b0 = v1.x, b1 = v1.y, b2 = v1.z, b3 = v1.w;
                uint4 ph, pl;
                ph.x = pack2_bf16(a0, b0); ph.y = pack2_bf16(a1, b1);
                ph.z = pack2_bf16(a2, b2); ph.w = pack2_bf16(a3, b3);
                pl.x = pack2_bf16(a0 - bf16_round(a0), b0 - bf16_round(b0));
                pl.y = pack2_bf16(a1 - bf16_round(a1), b1 - bf16_round(b1));
                pl.z = pack2_bf16(a2 - bf16_round(a2), b2 - bf16_round(b2));
                pl.w = pack2_bf16(a3 - bf16_round(a3), b3 - bf16_round(b3));
                int base = kp * SB32 + q * 4;
                *(uint4*)(Bh + base) = ph;
                *(uint4*)(Bl + base) = pl;
            }
        }
    };

    load_tile(0);

    for (int tt = 0; tt < ntiles; tt++) {
        __syncthreads();
        store_tile();
        __syncthreads();
        if (tt + 1 < ntiles) load_tile((tt + 1) * BK);

        #pragma unroll
        for (int kk = 0; kk < BK; kk += 16) {
            const int kp0 = kk / 2;
            uint32_t fah[MT][4], fal[MT][4], fbh[NT][2], fbl[NT][2];
            #pragma unroll
            for (int mi = 0; mi < MT; mi++) {
                int r = wm + mi * 16 + g;
                int b0 = r * SA32 + kp0 + t;
                int b1 = (r + 8) * SA32 + kp0 + t;
                fah[mi][0] = Ah[b0];     fah[mi][1] = Ah[b1];
                fah[mi][2] = Ah[b0 + 4]; fah[mi][3] = Ah[b1 + 4];
                fal[mi][0] = Al[b0];     fal[mi][1] = Al[b1];
                fal[mi][2] = Al[b0 + 4]; fal[mi][3] = Al[b1 + 4];
            }
            #pragma unroll
            for (int ni = 0; ni < NT; ni++) {
                int c = wn + ni * 8 + g;
                int b0 = (kp0 + t) * SB32 + c;
                int b1 = (kp0 + t + 4) * SB32 + c;
                fbh[ni][0] = Bh[b0]; fbh[ni][1] = Bh[b1];
                fbl[ni][0] = Bl[b0]; fbl[ni][1] = Bl[b1];
            }
            #pragma unroll
            for (int mi = 0; mi < MT; mi++)
                #pragma unroll
                for (int ni = 0; ni < NT; ni++) {
                    MMA_BF16(acc[mi][ni], fah[mi], fbh[ni]);
                    MMA_BF16(acc[mi][ni], fal[mi], fbh[ni]);
                    MMA_BF16(acc[mi][ni], fah[mi], fbl[ni]);
                }
        }
    }

    // epilogue
    #pragma unroll
    for (int mi = 0; mi < MT; mi++) {
        int r = row0 + wm + mi * 16 + g;
        #pragma unroll
        for (int ni = 0; ni < NT; ni++) {
            int c = wn + ni * 8 + 2 * t;
            float bx = 0.f, by = 0.f;
            if (BIAS) { bx = bias[c]; by = bias[c + 1]; }
            if (r < M)
                *(float2*)(C + (long)r * N + c) = make_float2(acc[mi][ni][0] + bx, acc[mi][ni][1] + by);
            if (r + 8 < M)
                *(float2*)(C + (long)(r + 8) * N + c) = make_float2(acc[mi][ni][2] + bx, acc[mi][ni][3] + by);
        }
    }
}

// ------------------------------ CSR SpMM -----------------------------------

template <bool RELU>
__global__ void spmm128_kernel(const float* __restrict__ support,
                               const int* __restrict__ offsets,
                               const int* __restrict__ col,
                               const float* __restrict__ val,
                               const float* __restrict__ bias,
                               float* __restrict__ out, int n) {
    int warp = (blockIdx.x * blockDim.x + threadIdx.x) >> 5;
    int lane = threadIdx.x & 31;
    if (warp >= n) return;
    int start = offsets[warp], end = offsets[warp + 1];
    const float4* sup4 = (const float4*)support;
    float4 acc = make_float4(0.f, 0.f, 0.f, 0.f);
    int j = start;
    for (; j + 2 <= end; j += 2) {
        int c0 = col[j], c1 = col[j + 1];
        float w0 = val[j], w1 = val[j + 1];
        float4 s0 = sup4[c0 * 32 + lane];
        float4 s1 = sup4[c1 * 32 + lane];
        acc.x += w0 * s0.x + w1 * s1.x;
        acc.y += w0 * s0.y + w1 * s1.y;
        acc.z += w0 * s0.z + w1 * s1.z;
        acc.w += w0 * s0.w + w1 * s1.w;
    }
    if (j < end) {
        int c = col[j]; float w = val[j];
        float4 s = sup4[c * 32 + lane];
        acc.x += w * s.x; acc.y += w * s.y; acc.z += w * s.z; acc.w += w * s.w;
    }
    float4 bb = ((const float4*)bias)[lane];
    acc.x += bb.x; acc.y += bb.y; acc.z += bb.z; acc.w += bb.w;
    if (RELU) {
        acc.x = fmaxf(acc.x, 0.f); acc.y = fmaxf(acc.y, 0.f);
        acc.z = fmaxf(acc.z, 0.f); acc.w = fmaxf(acc.w, 0.f);
    }
    ((float4*)out)[warp * 32 + lane] = acc;
}

template <bool RELU>
__global__ void spmm64_kernel(const float* __restrict__ support,
                              const int* __restrict__ offsets,
                              const int* __restrict__ col,
                              const float* __restrict__ val,
                              const float* __restrict__ bias,
                              float* __restrict__ out, int n) {
    int warp = (blockIdx.x * blockDim.x + threadIdx.x) >> 5;
    int lane = threadIdx.x & 31;
    if (warp >= n) return;
    int start = offsets[warp], end = offsets[warp + 1];
    const float2* sup2 = (const float2*)support;
    float2 acc = make_float2(0.f, 0.f);
    int j = start;
    for (; j + 2 <= end; j += 2) {
        int c0 = col[j], c1 = col[j + 1];
        float w0 = val[j], w1 = val[j + 1];
        float2 s0 = sup2[c0 * 32 + lane];
        float2 s1 = sup2[c1 * 32 + lane];
        acc.x += w0 * s0.x + w1 * s1.x;
        acc.y += w0 * s0.y + w1 * s1.y;
    }
    if (j < end) {
        int c = col[j]; float w = val[j];
        float2 s = sup2[c * 32 + lane];
        acc.x += w * s.x; acc.y += w * s.y;
    }
    float2 bb = ((const float2*)bias)[lane];
    acc.x += bb.x; acc.y += bb.y;
    if (RELU) { acc.x = fmaxf(acc.x, 0.f); acc.y = fmaxf(acc.y, 0.f); }
    ((float2*)out)[warp * 32 + lane] = acc;
}

__global__ void spmm16_lsm_kernel(const float* __restrict__ support,
                                  const int* __restrict__ offsets,
                                  const int* __restrict__ col,
                                  const float* __restrict__ val,
                                  const float* __restrict__ bias,
                                  float* __restrict__ out, int n) {
    int t = blockIdx.x * blockDim.x + threadIdx.x;
    int grp = t >> 4;
    int sub = t & 15;
    bool active = grp < n;
    int g2 = active ? grp : (n - 1);
    int start = offsets[g2], end = offsets[g2 + 1];
    float acc = 0.f;
    for (int j = start; j < end; j++)
        acc += val[j] * support[col[j] * 16 + sub];
    acc += bias[sub];
    float m = acc;
    #pragma unroll
    for (int off = 8; off >= 1; off >>= 1)
        m = fmaxf(m, __shfl_xor_sync(0xffffffffu, m, off, 16));
    float s = expf(acc - m);
    #pragma unroll
    for (int off = 8; off >= 1; off >>= 1)
        s += __shfl_xor_sync(0xffffffffu, s, off, 16);
    if (active) out[grp * 16 + sub] = acc - (logf(s) + m);
}

// ------------------------------ launch -------------------------------------

extern "C" void kernel_launch(void* const* d_in, const int* in_sizes, int n_in,
                              void* d_out, int out_size) {
    const float* x  = (const float*)d_in[0];
    const float* ev = (const float*)d_in[1];
    const float* W1 = (const float*)d_in[2];
    const float* b1 = (const float*)d_in[3];
    const float* W2 = (const float*)d_in[4];
    const float* b2 = (const float*)d_in[5];
    const float* W3 = (const float*)d_in[6];
    const float* b3 = (const float*)d_in[7];
    const float* We = (const float*)d_in[8];
    const float* be = (const float*)d_in[9];
    const int* esrc = (const int*)d_in[10];
    const int* edst = (const int*)d_in[11];

    const int N = NN;
    const int E = in_sizes[10];

    float* out1 = (float*)d_out;
    float* out2 = (float*)d_out + (long)N * 16;

    float *p_support, *p_h1, *p_h2, *p_val;
    int *p_counts, *p_offsets, *p_cursor, *p_col;
    cudaGetSymbolAddress((void**)&p_support, g_support);
    cudaGetSymbolAddress((void**)&p_h1, g_h1);
    cudaGetSymbolAddress((void**)&p_h2, g_h2);
    cudaGetSymbolAddress((void**)&p_counts, g_counts);
    cudaGetSymbolAddress((void**)&p_offsets, g_offsets);
    cudaGetSymbolAddress((void**)&p_cursor, g_cursor);
    cudaGetSymbolAddress((void**)&p_col, g_col);
    cudaGetSymbolAddress((void**)&p_val, g_val);

    constexpr int S1 = gemm_smem_bytes(128, 128, 32);  // ~38 KB
    constexpr int S2 = gemm_smem_bytes(128, 64, 32);   // ~29 KB
    constexpr int S3 = gemm_smem_bytes(128, 16, 32);   // ~22 KB
    cudaFuncSetAttribute(bf16_gemm_kernel<128, 128, 32, 4, 4, false>,
                         cudaFuncAttributeMaxDynamicSharedMemorySize, S1);
    cudaFuncSetAttribute(bf16_gemm_kernel<128, 64, 32, 4, 2, false>,
                         cudaFuncAttributeMaxDynamicSharedMemorySize, S2);
    cudaFuncSetAttribute(bf16_gemm_kernel<128, 64, 32, 4, 2, true>,
                         cudaFuncAttributeMaxDynamicSharedMemorySize, S2);
    cudaFuncSetAttribute(bf16_gemm_kernel<128, 16, 32, 8, 1, false>,
                         cudaFuncAttributeMaxDynamicSharedMemorySize, S3);

    // ---- CSR build ----
    cudaMemsetAsync(p_counts, 0, (N + 1) * sizeof(int), 0);
    cudaMemsetAsync(p_cursor, 0, N * sizeof(int), 0);
    hist_kernel<<<(E + 255) / 256, 256>>>(esrc, p_counts, E);
    scan_kernel<<<1, 1024>>>(p_counts, p_offsets, N);
    scatter_kernel<<<(E + 255) / 256, 256>>>(esrc, edst, ev, p_offsets, p_cursor, p_col, p_val, E);

    dim3 grid(1, (N + 127) / 128);

    // ---- layer 1: support = x@W1 [N,128]; h1 = relu(agg + b1) ----
    bf16_gemm_kernel<128, 128, 32, 4, 4, false><<<grid, 512, S1>>>(N, 128, 500, x, W1, nullptr, p_support);
    spmm128_kernel<true><<<(N * 32 + 255) / 256, 256>>>(p_support, p_offsets, p_col, p_val, b1, p_h1, N);

    // ---- layer 2: support = h1@W2 [N,64]; h2 = relu(agg + b2) ----
    bf16_gemm_kernel<128, 64, 32, 4, 2, false><<<grid, 256, S2>>>(N, 64, 128, p_h1, W2, nullptr, p_support);
    spmm64_kernel<true><<<(N * 32 + 255) / 256, 256>>>(p_support, p_offsets, p_col, p_val, b2, p_h2, N);

    // ---- layer 3: support = h2@W3 [N,16]; out1 = log_softmax(agg + b3) ----
    bf16_gemm_kernel<128, 16, 32, 8, 1, false><<<grid, 256, S3>>>(N, 16, 64, p_h2, W3, nullptr, p_support);
    spmm16_lsm_kernel<<<(N * 16 + 255) / 256, 256>>>(p_support, p_offsets, p_col, p_val, b3, out1, N);

    // ---- head 2: out2 = h2@We + be ----
    bf16_gemm_kernel<128, 64, 32, 4, 2, true><<<grid, 256, S2>>>(N, 64, 64, p_h2, We, be, out2);
}

// round 12
// speedup vs baseline: 2.2025x; 1.4067x over previous
#include <cuda_runtime.h>
#include <cuda_bf16.h>
#include <cstdint>
#include <stdint.h>
#include <math.h>

// ---------------------------------------------------------------------------
// GCN 3-layer. Round 11: GEMMs = mma.sync m16n8k16 bf16 3-term split, fed by
// a 3-stage cp.async pipeline of RAW fp32 tiles; bf16 hi/lo conversion happens
// at fragment-read time in registers. One __syncthreads per K-tile.
// CSR gather SpMM + fused spmm16+log_softmax as in the 310us config.
// ---------------------------------------------------------------------------

#define NN 50000
#define EE 800000

__device__ float g_support[NN * 128];
__device__ float g_h1[NN * 128];
__device__ float g_h2[NN * 64];
__device__ int   g_counts[NN + 1];
__device__ int   g_offsets[NN + 1];
__device__ int   g_cursor[NN];
__device__ int   g_col[EE];
__device__ float g_val[EE];

__device__ __forceinline__ uint32_t smem_u32(const void* p) {
    uint32_t a;
    asm("{ .reg .u64 t; cvta.to.shared.u64 t, %1; cvt.u32.u64 %0, t; }" : "=r"(a) : "l"(p));
    return a;
}

// ------------------------------ CSR build ----------------------------------

__global__ void hist_kernel(const int* __restrict__ src, int* __restrict__ counts, int E) {
    int i = blockIdx.x * blockDim.x + threadIdx.x;
    if (i < E) atomicAdd(&counts[src[i]], 1);
}

__global__ void scan_kernel(const int* __restrict__ counts, int* __restrict__ offsets, int n) {
    const int T = 1024;
    __shared__ int wsum[32];
    int tid = threadIdx.x;
    int per = (n + T - 1) / T;
    int beg = tid * per;
    int end = min(beg + per, n);
    int sum = 0;
    for (int i = beg; i < end; i++) sum += counts[i];
    int lane = tid & 31, wid = tid >> 5;
    int v = sum;
    #pragma unroll
    for (int off = 1; off < 32; off <<= 1) {
        int t2 = __shfl_up_sync(0xffffffffu, v, off);
        if (lane >= off) v += t2;
    }
    if (lane == 31) wsum[wid] = v;
    __syncthreads();
    if (wid == 0) {
        int w = wsum[lane];
        #pragma unroll
        for (int off = 1; off < 32; off <<= 1) {
            int t2 = __shfl_up_sync(0xffffffffu, w, off);
            if (lane >= off) w += t2;
        }
        wsum[lane] = w;
    }
    __syncthreads();
    int pre = v - sum + (wid > 0 ? wsum[wid - 1] : 0);
    int run = pre;
    for (int i = beg; i < end; i++) { offsets[i] = run; run += counts[i]; }
    if (end == n) offsets[n] = run;
}

__global__ void scatter_kernel(const int* __restrict__ src, const int* __restrict__ dst,
                               const float* __restrict__ ev,
                               const int* __restrict__ offsets, int* __restrict__ cursor,
                               int* __restrict__ col, float* __restrict__ val, int E) {
    int i = blockIdx.x * blockDim.x + threadIdx.x;
    if (i < E) {
        int s = src[i];
        int pos = offsets[s] + atomicAdd(&cursor[s], 1);
        col[pos] = dst[i];
        val[pos] = ev[i];
    }
}

// ------------------------------ bf16 GEMM (cp.async) -----------------------
// C[M,N] = A[M,K] @ B[K,N] (+bias). 3-term bf16 split built at frag-read
// time from raw fp32 smem tiles; 3-stage cp.async pipeline.
// Requires N == BN (grid.x == 1), K % 4 == 0.

// pack (x=k_even, y=k_odd) -> hi pair and lo (residual) pair
__device__ __forceinline__ void packpair(float x, float y, uint32_t& h, uint32_t& l) {
    uint32_t p;
    asm("cvt.rn.bf16x2.f32 %0, %1, %2;" : "=r"(p) : "f"(y), "f"(x));  // hi word = y
    float xr = __uint_as_float(p << 16);
    float yr = __uint_as_float(p & 0xffff0000u);
    uint32_t q;
    asm("cvt.rn.bf16x2.f32 %0, %1, %2;" : "=r"(q) : "f"(y - yr), "f"(x - xr));
    h = p; l = q;
}

#define MMA_BF16(c, a, b)                                                    \
    asm volatile(                                                            \
        "mma.sync.aligned.m16n8k16.row.col.f32.bf16.bf16.f32 "               \
        "{%0,%1,%2,%3}, {%4,%5,%6,%7}, {%8,%9}, {%0,%1,%2,%3};\n"            \
        : "+f"((c)[0]), "+f"((c)[1]), "+f"((c)[2]), "+f"((c)[3])             \
        : "r"((a)[0]), "r"((a)[1]), "r"((a)[2]), "r"((a)[3]),                \
          "r"((b)[0]), "r"((b)[1]))

#define CP_ASYNC16(dst, src, sz) \
    asm volatile("cp.async.cg.shared.global [%0], [%1], 16, %2;" \
                 :: "r"(dst), "l"(src), "r"(sz))
#define CP_COMMIT() asm volatile("cp.async.commit_group;" ::: "memory")

constexpr int gemm_smem_bytes(int BM, int BN, int BK, int NSTAGE) {
    int SA = BK + 4, SB = BN + 8;
    return NSTAGE * (BM * SA + BK * SB) * 4;
}

template <int BM, int BN, int BK, int WARPS_M, int WARPS_N, int NSTAGE, bool BIAS>
__global__ void __launch_bounds__(32 * WARPS_M * WARPS_N,
                                  (32 * WARPS_M * WARPS_N <= 256) ? 2 : 1)
bf16cp_gemm_kernel(int M, int N, int K,
                   const float* __restrict__ A, const float* __restrict__ B,
                   const float* __restrict__ bias, float* __restrict__ C) {
    constexpr int THREADS = 32 * WARPS_M * WARPS_N;
    constexpr int WM = BM / WARPS_M, WN = BN / WARPS_N;
    constexpr int MT = WM / 16, NT = WN / 8;
    constexpr int SA = BK + 4;                 // fp32 stride of A rows
    constexpr int SB = BN + 8;                 // fp32 stride of B rows
    constexpr int A_ST = BM * SA, B_ST = BK * SB;
    constexpr int AITEMS = BM * BK / 4;
    constexpr int BITEMS = BK * BN / 4;

    extern __shared__ float smemf[];

    const int tid = threadIdx.x;
    const int warp = tid >> 5, lane = tid & 31;
    const int wm = (warp / WARPS_N) * WM;
    const int wn = (warp % WARPS_N) * WN;
    const int g = lane >> 2, tq = lane & 3;
    const int row0 = blockIdx.y * BM;
    const int ntiles = (K + BK - 1) / BK;

    float acc[MT][NT][4];
    #pragma unroll
    for (int mi = 0; mi < MT; mi++)
        #pragma unroll
        for (int ni = 0; ni < NT; ni++)
            #pragma unroll
            for (int q = 0; q < 4; q++) acc[mi][ni][q] = 0.f;

    auto issue_tile = [&](int tile) {
        if (tile >= ntiles) return;
        int k0 = tile * BK;
        float* as = smemf + (tile % NSTAGE) * (A_ST + B_ST);
        float* bs = as + A_ST;
        #pragma unroll
        for (int i = tid; i < AITEMS; i += THREADS) {
            int r = i / (BK / 4), q = i % (BK / 4);
            int gm = row0 + r, gk = k0 + q * 4;
            uint32_t dst = smem_u32(as + r * SA + q * 4);
            const float* src = A + (long)gm * K + gk;
            int sz = (gm < M && gk < K) ? 16 : 0;
            CP_ASYNC16(dst, src, sz);
        }
        #pragma unroll
        for (int i = tid; i < BITEMS; i += THREADS) {
            int r = i / (BN / 4), q = i % (BN / 4);
            int gk = k0 + r;
            uint32_t dst = smem_u32(bs + r * SB + q * 4);
            const float* src = B + (long)gk * N + q * 4;
            int sz = (gk < K) ? 16 : 0;
            CP_ASYNC16(dst, src, sz);
        }
    };

    // prologue: NSTAGE-1 tiles in flight
    #pragma unroll
    for (int s = 0; s < NSTAGE - 1; s++) { issue_tile(s); CP_COMMIT(); }

    for (int t = 0; t < ntiles; t++) {
        asm volatile("cp.async.wait_group %0;" :: "n"(NSTAGE - 2) : "memory");
        __syncthreads();
        issue_tile(t + NSTAGE - 1);
        CP_COMMIT();

        const float* as = smemf + (t % NSTAGE) * (A_ST + B_ST);
        const float* bs = as + A_ST;

        #pragma unroll
        for (int kk = 0; kk < BK; kk += 16) {
            uint32_t fah[MT][4], fal[MT][4], fbh[NT][2], fbl[NT][2];
            #pragma unroll
            for (int mi = 0; mi < MT; mi++) {
                int r = wm + mi * 16 + g;
                float2 a0 = *(const float2*)(as + r * SA + kk + 2 * tq);
                float2 a1 = *(const float2*)(as + (r + 8) * SA + kk + 2 * tq);
                float2 a2 = *(const float2*)(as + r * SA + kk + 2 * tq + 8);
                float2 a3 = *(const float2*)(as + (r + 8) * SA + kk + 2 * tq + 8);
                packpair(a0.x, a0.y, fah[mi][0], fal[mi][0]);
                packpair(a1.x, a1.y, fah[mi][1], fal[mi][1]);
                packpair(a2.x, a2.y, fah[mi][2], fal[mi][2]);
                packpair(a3.x, a3.y, fah[mi][3], fal[mi][3]);
            }
            #pragma unroll
            for (int ni = 0; ni < NT; ni++) {
                int c = wn + ni * 8 + g;
                float b00 = bs[(kk + 2 * tq) * SB + c];
                float b01 = bs[(kk + 2 * tq + 1) * SB + c];
                float b10 = bs[(kk + 2 * tq + 8) * SB + c];
                float b11 = bs[(kk + 2 * tq + 9) * SB + c];
                packpair(b00, b01, fbh[ni][0], fbl[ni][0]);
                packpair(b10, b11, fbh[ni][1], fbl[ni][1]);
            }
            #pragma unroll
            for (int mi = 0; mi < MT; mi++)
                #pragma unroll
                for (int ni = 0; ni < NT; ni++) {
                    MMA_BF16(acc[mi][ni], fah[mi], fbh[ni]);
                    MMA_BF16(acc[mi][ni], fal[mi], fbh[ni]);
                    MMA_BF16(acc[mi][ni], fah[mi], fbl[ni]);
                }
        }
    }

    // epilogue
    #pragma unroll
    for (int mi = 0; mi < MT; mi++) {
        int r = row0 + wm + mi * 16 + g;
        #pragma unroll
        for (int ni = 0; ni < NT; ni++) {
            int c = wn + ni * 8 + 2 * tq;
            float bx = 0.f, by = 0.f;
            if (BIAS) { bx = bias[c]; by = bias[c + 1]; }
            if (r < M)
                *(float2*)(C + (long)r * N + c) = make_float2(acc[mi][ni][0] + bx, acc[mi][ni][1] + by);
            if (r + 8 < M)
                *(float2*)(C + (long)(r + 8) * N + c) = make_float2(acc[mi][ni][2] + bx, acc[mi][ni][3] + by);
        }
    }
}

// ------------------------------ CSR SpMM -----------------------------------

template <bool RELU>
__global__ void spmm128_kernel(const float* __restrict__ support,
                               const int* __restrict__ offsets,
                               const int* __restrict__ col,
                               const float* __restrict__ val,
                               const float* __restrict__ bias,
                               float* __restrict__ out, int n) {
    int warp = (blockIdx.x * blockDim.x + threadIdx.x) >> 5;
    int lane = threadIdx.x & 31;
    if (warp >= n) return;
    int start = offsets[warp], end = offsets[warp + 1];
    const float4* sup4 = (const float4*)support;
    float4 acc = make_float4(0.f, 0.f, 0.f, 0.f);
    int j = start;
    for (; j + 2 <= end; j += 2) {
        int c0 = col[j], c1 = col[j + 1];
        float w0 = val[j], w1 = val[j + 1];
        float4 s0 = sup4[c0 * 32 + lane];
        float4 s1 = sup4[c1 * 32 + lane];
        acc.x += w0 * s0.x + w1 * s1.x;
        acc.y += w0 * s0.y + w1 * s1.y;
        acc.z += w0 * s0.z + w1 * s1.z;
        acc.w += w0 * s0.w + w1 * s1.w;
    }
    if (j < end) {
        int c = col[j]; float w = val[j];
        float4 s = sup4[c * 32 + lane];
        acc.x += w * s.x; acc.y += w * s.y; acc.z += w * s.z; acc.w += w * s.w;
    }
    float4 bb = ((const float4*)bias)[lane];
    acc.x += bb.x; acc.y += bb.y; acc.z += bb.z; acc.w += bb.w;
    if (RELU) {
        acc.x = fmaxf(acc.x, 0.f); acc.y = fmaxf(acc.y, 0.f);
        acc.z = fmaxf(acc.z, 0.f); acc.w = fmaxf(acc.w, 0.f);
    }
    ((float4*)out)[warp * 32 + lane] = acc;
}

template <bool RELU>
__global__ void spmm64_kernel(const float* __restrict__ support,
                              const int* __restrict__ offsets,
                              const int* __restrict__ col,
                              const float* __restrict__ val,
                              const float* __restrict__ bias,
                              float* __restrict__ out, int n) {
    int warp = (blockIdx.x * blockDim.x + threadIdx.x) >> 5;
    int lane = threadIdx.x & 31;
    if (warp >= n) return;
    int start = offsets[warp], end = offsets[warp + 1];
    const float2* sup2 = (const float2*)support;
    float2 acc = make_float2(0.f, 0.f);
    int j = start;
    for (; j + 2 <= end; j += 2) {
        int c0 = col[j], c1 = col[j + 1];
        float w0 = val[j], w1 = val[j + 1];
        float2 s0 = sup2[c0 * 32 + lane];
        float2 s1 = sup2[c1 * 32 + lane];
        acc.x += w0 * s0.x + w1 * s1.x;
        acc.y += w0 * s0.y + w1 * s1.y;
    }
    if (j < end) {
        int c = col[j]; float w = val[j];
        float2 s = sup2[c * 32 + lane];
        acc.x += w * s.x; acc.y += w * s.y;
    }
    float2 bb = ((const float2*)bias)[lane];
    acc.x += bb.x; acc.y += bb.y;
    if (RELU) { acc.x = fmaxf(acc.x, 0.f); acc.y = fmaxf(acc.y, 0.f); }
    ((float2*)out)[warp * 32 + lane] = acc;
}

__global__ void spmm16_lsm_kernel(const float* __restrict__ support,
                                  const int* __restrict__ offsets,
                                  const int* __restrict__ col,
                                  const float* __restrict__ val,
                                  const float* __restrict__ bias,
                                  float* __restrict__ out, int n) {
    int t = blockIdx.x * blockDim.x + threadIdx.x;
    int grp = t >> 4;
    int sub = t & 15;
    bool active = grp < n;
    int g2 = active ? grp : (n - 1);
    int start = offsets[g2], end = offsets[g2 + 1];
    float acc = 0.f;
    for (int j = start; j < end; j++)
        acc += val[j] * support[col[j] * 16 + sub];
    acc += bias[sub];
    float m = acc;
    #pragma unroll
    for (int off = 8; off >= 1; off >>= 1)
        m = fmaxf(m, __shfl_xor_sync(0xffffffffu, m, off, 16));
    float s = expf(acc - m);
    #pragma unroll
    for (int off = 8; off >= 1; off >>= 1)
        s += __shfl_xor_sync(0xffffffffu, s, off, 16);
    if (active) out[grp * 16 + sub] = acc - (logf(s) + m);
}

// ------------------------------ launch -------------------------------------

extern "C" void kernel_launch(void* const* d_in, const int* in_sizes, int n_in,
                              void* d_out, int out_size) {
    const float* x  = (const float*)d_in[0];
    const float* ev = (const float*)d_in[1];
    const float* W1 = (const float*)d_in[2];
    const float* b1 = (const float*)d_in[3];
    const float* W2 = (const float*)d_in[4];
    const float* b2 = (const float*)d_in[5];
    const float* W3 = (const float*)d_in[6];
    const float* b3 = (const float*)d_in[7];
    const float* We = (const float*)d_in[8];
    const float* be = (const float*)d_in[9];
    const int* esrc = (const int*)d_in[10];
    const int* edst = (const int*)d_in[11];

    const int N = NN;
    const int E = in_sizes[10];

    float* out1 = (float*)d_out;
    float* out2 = (float*)d_out + (long)N * 16;

    float *p_support, *p_h1, *p_h2, *p_val;
    int *p_counts, *p_offsets, *p_cursor, *p_col;
    cudaGetSymbolAddress((void**)&p_support, g_support);
    cudaGetSymbolAddress((void**)&p_h1, g_h1);
    cudaGetSymbolAddress((void**)&p_h2, g_h2);
    cudaGetSymbolAddress((void**)&p_counts, g_counts);
    cudaGetSymbolAddress((void**)&p_offsets, g_offsets);
    cudaGetSymbolAddress((void**)&p_cursor, g_cursor);
    cudaGetSymbolAddress((void**)&p_col, g_col);
    cudaGetSymbolAddress((void**)&p_val, g_val);

    constexpr int S1 = gemm_smem_bytes(128, 128, 32, 3);  // 107520
    constexpr int S2 = gemm_smem_bytes(128, 64, 32, 3);   // 82944
    constexpr int S3 = gemm_smem_bytes(128, 16, 32, 3);   // 64512
    cudaFuncSetAttribute(bf16cp_gemm_kernel<128, 128, 32, 4, 4, 3, false>,
                         cudaFuncAttributeMaxDynamicSharedMemorySize, S1);
    cudaFuncSetAttribute(bf16cp_gemm_kernel<128, 64, 32, 4, 2, 3, false>,
                         cudaFuncAttributeMaxDynamicSharedMemorySize, S2);
    cudaFuncSetAttribute(bf16cp_gemm_kernel<128, 64, 32, 4, 2, 3, true>,
                         cudaFuncAttributeMaxDynamicSharedMemorySize, S2);
    cudaFuncSetAttribute(bf16cp_gemm_kernel<128, 16, 32, 8, 1, 3, false>,
                         cudaFuncAttributeMaxDynamicSharedMemorySize, S3);

    // ---- CSR build ----
    cudaMemsetAsync(p_counts, 0, (N + 1) * sizeof(int), 0);
    cudaMemsetAsync(p_cursor, 0, N * sizeof(int), 0);
    hist_kernel<<<(E + 255) / 256, 256>>>(esrc, p_counts, E);
    scan_kernel<<<1, 1024>>>(p_counts, p_offsets, N);
    scatter_kernel<<<(E + 255) / 256, 256>>>(esrc, edst, ev, p_offsets, p_cursor, p_col, p_val, E);

    dim3 grid(1, (N + 127) / 128);

    // ---- layer 1: support = x@W1 [N,128]; h1 = relu(agg + b1) ----
    bf16cp_gemm_kernel<128, 128, 32, 4, 4, 3, false><<<grid, 512, S1>>>(N, 128, 500, x, W1, nullptr, p_support);
    spmm128_kernel<true><<<(N * 32 + 255) / 256, 256>>>(p_support, p_offsets, p_col, p_val, b1, p_h1, N);

    // ---- layer 2: support = h1@W2 [N,64]; h2 = relu(agg + b2) ----
    bf16cp_gemm_kernel<128, 64, 32, 4, 2, 3, false><<<grid, 256, S2>>>(N, 64, 128, p_h1, W2, nullptr, p_support);
    spmm64_kernel<true><<<(N * 32 + 255) / 256, 256>>>(p_support, p_offsets, p_col, p_val, b2, p_h2, N);

    // ---- layer 3: support = h2@W3 [N,16]; out1 = log_softmax(agg + b3) ----
    bf16cp_gemm_kernel<128, 16, 32, 8, 1, 3, false><<<grid, 256, S3>>>(N, 16, 64, p_h2, W3, nullptr, p_support);
    spmm16_lsm_kernel<<<(N * 16 + 255) / 256, 256>>>(p_support, p_offsets, p_col, p_val, b3, out1, N);

    // ---- head 2: out2 = h2@We + be ----
    bf16cp_gemm_kernel<128, 64, 32, 4, 2, 3, true><<<grid, 256, S2>>>(N, 64, 64, p_h2, We, be, out2);
}